// round 15
// baseline (speedup 1.0000x reference)
#include <cuda_runtime.h>
#include <cuda_bf16.h>
#include <math.h>
#include <stdint.h>

#define BATCH 16
#define SEQ   1024
#define DMODEL 512
#define NHEAD 4
#define HDIM  128
#define MROWS (BATCH * SEQ)
#define DMLP  1024

typedef __nv_bfloat16 bf16;

__device__ bf16  g_x1n [MROWS * DMODEL];
__device__ bf16  g_x2n [MROWS * DMODEL];
__device__ bf16  g_q1  [MROWS * DMODEL];
__device__ bf16  g_k1  [MROWS * DMODEL];
__device__ bf16  g_v1  [MROWS * DMODEL];
__device__ bf16  g_q2  [MROWS * DMODEL];
__device__ bf16  g_k2  [MROWS * DMODEL];
__device__ bf16  g_v2  [MROWS * DMODEL];
__device__ bf16  g_ctx1[MROWS * DMODEL];
__device__ bf16  g_ctx2[MROWS * DMODEL];
__device__ bf16  g_src1[MROWS * DMODEL];
__device__ bf16  g_src2[MROWS * DMODEL];
__device__ float g_xres[MROWS * DMODEL];
__device__ bf16  g_h   [MROWS * DMLP];
__device__ bf16  g_wr  [3670016];
__device__ float g_bqkv[4608];

__device__ __forceinline__ uint32_t s2u(const void* p) {
    return (uint32_t)__cvta_generic_to_shared(p);
}
__device__ __forceinline__ void cpa16(uint32_t dst, const void* src) {
    asm volatile("cp.async.cg.shared.global [%0], [%1], 16;" :: "r"(dst), "l"(src));
}
#define CP_COMMIT() asm volatile("cp.async.commit_group;")
template <int N> __device__ __forceinline__ void cp_wait() {
    asm volatile("cp.async.wait_group %0;" :: "n"(N));
}
__device__ __forceinline__ void ldsm4(uint32_t* r, uint32_t a) {
    asm volatile("ldmatrix.sync.aligned.m8n8.x4.shared.b16 {%0,%1,%2,%3}, [%4];"
                 : "=r"(r[0]), "=r"(r[1]), "=r"(r[2]), "=r"(r[3]) : "r"(a));
}
__device__ __forceinline__ void ldsm4t(uint32_t* r, uint32_t a) {
    asm volatile("ldmatrix.sync.aligned.m8n8.x4.trans.shared.b16 {%0,%1,%2,%3}, [%4];"
                 : "=r"(r[0]), "=r"(r[1]), "=r"(r[2]), "=r"(r[3]) : "r"(a));
}
__device__ __forceinline__ void mma_bf(float* c, const uint32_t* a, const uint32_t* b) {
    asm volatile(
        "mma.sync.aligned.m16n8k16.row.col.f32.bf16.bf16.f32 "
        "{%0,%1,%2,%3}, {%4,%5,%6,%7}, {%8,%9}, {%0,%1,%2,%3};"
        : "+f"(c[0]), "+f"(c[1]), "+f"(c[2]), "+f"(c[3])
        : "r"(a[0]), "r"(a[1]), "r"(a[2]), "r"(a[3]), "r"(b[0]), "r"(b[1]));
}
__device__ __forceinline__ uint32_t packbf(float x, float y) {
    __nv_bfloat162 h = __floats2bfloat162_rn(x, y);
    return *(uint32_t*)&h;
}

// -------- weight repack ------------------------------------------------------
struct WPtrs { const float* s[12]; };
__global__ void round_w(WPtrs p, bf16* dst, float qs) {
    int t = blockIdx.x * blockDim.x + threadIdx.x;
    int idx = t * 8;
    if (idx >= 3670016) return;
    const float* src; float sc = 1.f; int off;
    if (idx < 2359296) {
        int s = idx / 786432, rem = idx % 786432;
        int kk = rem / 1536, n = rem % 1536;
        int m = n >> 9;
        src = p.s[s * 3 + m];
        off = kk * 512 + (n & 511);
        if (m == 0) sc = qs;
    } else if (idx < 2621440) { src = p.s[9];  off = idx - 2359296; }
    else if (idx < 3145728)   { src = p.s[10]; off = idx - 2621440; }
    else                      { src = p.s[11]; off = idx - 3145728; }
    float4 v0 = *(const float4*)&src[off];
    float4 v1 = *(const float4*)&src[off + 4];
    uint32_t h[4] = { packbf(v0.x*sc, v0.y*sc), packbf(v0.z*sc, v0.w*sc),
                      packbf(v1.x*sc, v1.y*sc), packbf(v1.z*sc, v1.w*sc) };
    *(uint4*)&dst[idx] = *(uint4*)h;
}

struct BPtrs { const float* s[9]; };
__global__ void round_b(BPtrs p, float* dst, float qs) {
    int i = blockIdx.x * blockDim.x + threadIdx.x;
    if (i >= 4608) return;
    int s = i / 1536, n = i % 1536, m = n >> 9;
    float v = p.s[s * 3 + m][n & 511];
    dst[i] = (m == 0) ? v * qs : v;
}

// -------- dual LayerNorm -----------------------------------------------------
struct LnA { const float* x[2]; const float* g[2]; const float* b[2]; bf16* y[2]; };
__global__ void ln2_kernel(LnA a) {
    int row = blockIdx.x, t = threadIdx.x;
    int si = row >> 14; row &= (MROWS - 1);
    const float* xr = a.x[si] + (size_t)row * DMODEL;
    float4 v4 = ((const float4*)xr)[t];
    __shared__ float red[4];
    float s = v4.x + v4.y + v4.z + v4.w;
    #pragma unroll
    for (int o = 16; o; o >>= 1) s += __shfl_xor_sync(0xffffffffu, s, o);
    if ((t & 31) == 0) red[t >> 5] = s;
    __syncthreads();
    float mean = (red[0] + red[1] + red[2] + red[3]) * (1.0f / DMODEL);
    __syncthreads();
    float dx = v4.x - mean, dy = v4.y - mean, dz = v4.z - mean, dw = v4.w - mean;
    float vs = dx*dx + dy*dy + dz*dz + dw*dw;
    #pragma unroll
    for (int o = 16; o; o >>= 1) vs += __shfl_xor_sync(0xffffffffu, vs, o);
    if ((t & 31) == 0) red[t >> 5] = vs;
    __syncthreads();
    float var = (red[0] + red[1] + red[2] + red[3]) * (1.0f / DMODEL);
    float inv = rsqrtf(var + 1e-6f);
    float4 g4 = ((const float4*)a.g[si])[t];
    float4 b4 = ((const float4*)a.b[si])[t];
    uint32_t h[2] = { packbf(dx * inv * g4.x + b4.x, dy * inv * g4.y + b4.y),
                      packbf(dz * inv * g4.z + b4.z, dw * inv * g4.w + b4.w) };
    *(uint2*)&a.y[si][(size_t)row * DMODEL + t * 4] = *(uint2*)h;
}

// -------- GEMM tile machinery (BK=64) ---------------------------------------
#define GAB (128 * 144)
#define GBB (64 * 272)
#define GEMM_SMEM (2 * (GAB + GBB))

__device__ __forceinline__ void g_stage(uint32_t smA, uint32_t smB, int buf,
                                        const bf16* A, const bf16* W,
                                        int m0, int n0, int k0, int K, int N, int tid) {
    int ar = tid >> 1, ag = (tid & 1) * 4;
    uint32_t da = smA + buf * GAB + ar * 144 + ag * 16;
    const bf16* sa = A + (size_t)(m0 + ar) * K + k0 + ag * 8;
    #pragma unroll
    for (int i = 0; i < 4; i++) cpa16(da + i * 16, sa + i * 8);
    int br = tid >> 2, bg = (tid & 3) * 4;
    uint32_t db = smB + buf * GBB + br * 272 + bg * 16;
    const bf16* sb = W + (size_t)(k0 + br) * N + n0 + bg * 8;
    #pragma unroll
    for (int i = 0; i < 4; i++) cpa16(db + i * 16, sb + i * 8);
    CP_COMMIT();
}

__device__ __forceinline__ void g_tile(float acc[4][4][4], uint32_t Ab, uint32_t Bb,
                                       int wm, int wn, int l15, int lh8) {
    #pragma unroll
    for (int kk = 0; kk < 64; kk += 16) {
        uint32_t a[4][4];
        #pragma unroll
        for (int mf = 0; mf < 4; mf++)
            ldsm4(a[mf], Ab + ((wm + mf * 16 + l15) * 72 + kk + lh8) * 2);
        #pragma unroll
        for (int nb = 0; nb < 2; nb++) {
            uint32_t b[4];
            ldsm4t(b, Bb + ((kk + l15) * 136 + wn + nb * 16 + lh8) * 2);
            #pragma unroll
            for (int mf = 0; mf < 4; mf++) {
                mma_bf(acc[mf][nb * 2 + 0], a[mf], b + 0);
                mma_bf(acc[mf][nb * 2 + 1], a[mf], b + 2);
            }
        }
    }
}

#define G_PROLOG_COMPUTE(Aptr, Wptr, Nval, Kval)                               \
    float acc[4][4][4];                                                        \
    _Pragma("unroll")                                                          \
    for (int i = 0; i < 4; i++)                                                \
        _Pragma("unroll")                                                      \
        for (int j = 0; j < 4; j++)                                            \
            _Pragma("unroll")                                                  \
            for (int kq = 0; kq < 4; kq++) acc[i][j][kq] = 0.f;                \
    g_stage(smA, smB, 0, Aptr, Wptr, m0, n0, 0, Kval, Nval, tid);              \
    int T = (Kval) >> 6, l15 = lane & 15, lh8 = (lane >> 4) << 3;              \
    for (int it = 0; it < T; it++) {                                           \
        cp_wait<0>();                                                          \
        __syncthreads();                                                       \
        if (it + 1 < T)                                                        \
            g_stage(smA, smB, (it + 1) & 1, Aptr, Wptr, m0, n0,                \
                    (it + 1) * 64, Kval, Nval, tid);                           \
        g_tile(acc, smA + (it & 1) * GAB, smB + (it & 1) * GBB,                \
               wm, wn, l15, lh8);                                              \
        __syncthreads();                                                       \
    }

// -------- generic GEMM (MLP / cross-Wo) -------------------------------------
template<int OUTF32>
__global__ __launch_bounds__(256, 2)
void gemm_bf(const bf16* __restrict__ A, const bf16* __restrict__ W,
             const float* __restrict__ bias,
             const bf16* __restrict__ residh, const float* __restrict__ residf,
             float* __restrict__ Cf, bf16* __restrict__ Ch,
             int M, int N, int K, int gelu) {
    extern __shared__ char smraw[];
    uint32_t smA = s2u(smraw);
    uint32_t smB = smA + 2 * GAB;
    int tid = threadIdx.x, lane = tid & 31, wid = tid >> 5;
    int m0 = blockIdx.y * 128, n0 = blockIdx.x * 128;
    int wm = (wid & 1) * 64, wn = (wid >> 1) * 32;

    G_PROLOG_COMPUTE(A, W, N, K)

    int r4 = lane >> 2, c2 = (lane & 3) * 2;
    #pragma unroll
    for (int mf = 0; mf < 4; mf++) {
        #pragma unroll
        for (int nf = 0; nf < 4; nf++) {
            int row = m0 + wm + mf * 16 + r4;
            int col = n0 + wn + nf * 8 + c2;
            float2 bi = *(const float2*)&bias[col];
            #pragma unroll
            for (int hh = 0; hh < 2; hh++) {
                int r = row + hh * 8;
                float v0 = acc[mf][nf][hh * 2 + 0] + bi.x;
                float v1 = acc[mf][nf][hh * 2 + 1] + bi.y;
                if (residh) {
                    uint32_t rp = *(const uint32_t*)&residh[(size_t)r * N + col];
                    float2 rr = __bfloat1622float2(*(__nv_bfloat162*)&rp);
                    v0 += rr.x; v1 += rr.y;
                }
                if (residf) {
                    float2 rr = *(const float2*)&residf[(size_t)r * N + col];
                    v0 += rr.x; v1 += rr.y;
                }
                if (gelu) {
                    v0 = 0.5f * v0 * (1.0f + erff(v0 * 0.70710678118654752f));
                    v1 = 0.5f * v1 * (1.0f + erff(v1 * 0.70710678118654752f));
                }
                if (OUTF32) *(float2*)&Cf[(size_t)r * N + col] = make_float2(v0, v1);
                else *(uint32_t*)&Ch[(size_t)r * N + col] = packbf(v0, v1);
            }
        }
    }
}

// -------- fused QKV GEMM: 256m x 128n tile, warp tile 64x64, 256 thr ---------
#define QAB (256 * 144)
#define QBB (64 * 272)
#define QKV_SMEM (2 * (QAB + QBB))

struct QkvA {
    const bf16* Aq[2]; const bf16* Akv[2]; const bf16* W[2];
    const float* bias[2]; bf16* q[2]; bf16* k[2]; bf16* v[2];
};
__global__ __launch_bounds__(256, 1)
void gemm_qkv(QkvA p, int ntiles) {
    const int K = DMODEL, N = 1536;
    extern __shared__ char smraw[];
    uint32_t smA = s2u(smraw);
    uint32_t smB = smA + 2 * QAB;
    int tid = threadIdx.x, lane = tid & 31, wid = tid >> 5;   // wid 0..7
    int si = blockIdx.x / ntiles;
    int n0 = (blockIdx.x % ntiles) * 128;
    int m0 = blockIdx.y * 256;
    const bf16* A = (n0 < 512) ? p.Aq[si] : p.Akv[si];
    const bf16* W = p.W[si];
    int wm = (wid & 3) * 64, wn = (wid >> 2) * 64;   // warp 64m x 64n
    int l15 = lane & 15, lh8 = (lane >> 4) << 3;

    float acc[4][8][4];
    #pragma unroll
    for (int i = 0; i < 4; i++)
        #pragma unroll
        for (int j = 0; j < 8; j++)
            #pragma unroll
            for (int kq = 0; kq < 4; kq++) acc[i][j][kq] = 0.f;

    // staging: A thread stages its whole 128B row (256 rows), B 64B/thread
    auto stage = [&](int buf, int k0) {
        uint32_t da = smA + buf * QAB + tid * 144;
        const bf16* sa = A + (size_t)(m0 + tid) * K + k0;
        #pragma unroll
        for (int i = 0; i < 8; i++) cpa16(da + i * 16, sa + i * 8);
        int br = tid >> 2, bg = (tid & 3) * 4;
        uint32_t db = smB + buf * QBB + br * 272 + bg * 16;
        const bf16* sb = W + (size_t)(k0 + br) * N + n0 + bg * 8;
        #pragma unroll
        for (int i = 0; i < 4; i++) cpa16(db + i * 16, sb + i * 8);
        CP_COMMIT();
    };

    stage(0, 0);
    const int T = K >> 6;
    for (int it = 0; it < T; it++) {
        cp_wait<0>();
        __syncthreads();
        if (it + 1 < T) stage((it + 1) & 1, (it + 1) * 64);
        uint32_t Ab = smA + (it & 1) * QAB;
        uint32_t Bb = smB + (it & 1) * QBB;
        #pragma unroll
        for (int kk = 0; kk < 64; kk += 16) {
            uint32_t a[4][4];
            #pragma unroll
            for (int mf = 0; mf < 4; mf++)
                ldsm4(a[mf], Ab + ((wm + mf * 16 + l15) * 72 + kk + lh8) * 2);
            #pragma unroll
            for (int nb = 0; nb < 4; nb++) {
                uint32_t b[4];
                ldsm4t(b, Bb + ((kk + l15) * 136 + wn + nb * 16 + lh8) * 2);
                #pragma unroll
                for (int mf = 0; mf < 4; mf++) {
                    mma_bf(acc[mf][nb * 2 + 0], a[mf], b + 0);
                    mma_bf(acc[mf][nb * 2 + 1], a[mf], b + 2);
                }
            }
        }
        __syncthreads();
    }

    int r4 = lane >> 2, c2 = (lane & 3) * 2;
    #pragma unroll
    for (int mf = 0; mf < 4; mf++) {
        #pragma unroll
        for (int nf = 0; nf < 8; nf++) {
            int row = m0 + wm + mf * 16 + r4;
            int col = n0 + wn + nf * 8 + c2;
            bf16* dst = (col < 512) ? p.q[si] : (col < 1024) ? p.k[si] : p.v[si];
            int cc = col & 511;
            float2 bi = *(const float2*)&p.bias[si][col];
            #pragma unroll
            for (int hh = 0; hh < 2; hh++) {
                int r = row + hh * 8;
                float v0 = acc[mf][nf][hh * 2 + 0] + bi.x;
                float v1 = acc[mf][nf][hh * 2 + 1] + bi.y;
                *(uint32_t*)&dst[(size_t)r * DMODEL + cc] = packbf(v0, v1);
            }
        }
    }
}

// -------- fused Wo GEMM, dual-stream -----------------------------------------
struct WoA { const bf16* A[2]; const bf16* resid[2]; bf16* out[2]; };
__global__ __launch_bounds__(256, 2)
void gemm_wo(WoA p, const bf16* __restrict__ W, const float* __restrict__ bias) {
    const int K = DMODEL, N = DMODEL;
    extern __shared__ char smraw[];
    uint32_t smA = s2u(smraw);
    uint32_t smB = smA + 2 * GAB;
    int tid = threadIdx.x, lane = tid & 31, wid = tid >> 5;
    int si = blockIdx.x >> 2;
    int n0 = (blockIdx.x & 3) * 128, m0 = blockIdx.y * 128;
    const bf16* A = p.A[si];
    int wm = (wid & 1) * 64, wn = (wid >> 1) * 32;

    G_PROLOG_COMPUTE(A, W, N, K)

    int r4 = lane >> 2, c2 = (lane & 3) * 2;
    #pragma unroll
    for (int mf = 0; mf < 4; mf++) {
        #pragma unroll
        for (int nf = 0; nf < 4; nf++) {
            int row = m0 + wm + mf * 16 + r4;
            int col = n0 + wn + nf * 8 + c2;
            float2 bi = *(const float2*)&bias[col];
            #pragma unroll
            for (int hh = 0; hh < 2; hh++) {
                int r = row + hh * 8;
                uint32_t rp = *(const uint32_t*)&p.resid[si][(size_t)r * N + col];
                float2 rr = __bfloat1622float2(*(__nv_bfloat162*)&rp);
                float v0 = acc[mf][nf][hh * 2 + 0] + bi.x + rr.x;
                float v1 = acc[mf][nf][hh * 2 + 1] + bi.y + rr.y;
                *(uint32_t*)&p.out[si][(size_t)r * N + col] = packbf(v0, v1);
            }
        }
    }
}

// -------- bf16 flash attention (R11 form) ------------------------------------
#define AQB (128 * 272)
#define AKB (64 * 272)
#define AVB (64 * 272)
#define ATT_SMEM (AQB + 2 * AKB + 2 * AVB)
#define NIT (SEQ / 64)

struct AttA { const bf16* Q[2]; const bf16* K[2]; const bf16* V[2]; bf16* O[2]; };
__global__ __launch_bounds__(256, 2)
void attn_bf(AttA p) {
    extern __shared__ char smraw[];
    uint32_t smQ = s2u(smraw);
    uint32_t smK = smQ + AQB;
    uint32_t smV = smK + 2 * AKB;

    int tid = threadIdx.x, lane = tid & 31, wid = tid >> 5;
    int q0 = blockIdx.x * 128, h = blockIdx.y;
    int zi = blockIdx.z;
    int si = zi >> 4, b = zi & 15;
    const bf16* Q = p.Q[si];
    const bf16* K = p.K[si];
    const bf16* V = p.V[si];
    bf16* O = p.O[si];
    size_t gq  = ((size_t)b * SEQ + q0) * DMODEL + (size_t)h * HDIM;
    size_t gk0 = ((size_t)b * SEQ) * DMODEL + (size_t)h * HDIM;
    int sr = tid >> 4, sg = tid & 15;

    #pragma unroll
    for (int i = 0; i < 8; i++) {
        int r = sr + 16 * i;
        cpa16(smQ + r * 272 + sg * 16, Q + gq + (size_t)r * DMODEL + sg * 8);
    }
    CP_COMMIT();
    #pragma unroll
    for (int i = 0; i < 4; i++) {
        int r = sr + 16 * i;
        cpa16(smK + r * 272 + sg * 16, K + gk0 + (size_t)r * DMODEL + sg * 8);
        cpa16(smV + r * 272 + sg * 16, V + gk0 + (size_t)r * DMODEL + sg * 8);
    }
    CP_COMMIT();
    cp_wait<0>();
    __syncthreads();

    float mrow[2] = {-1e30f, -1e30f}, lrow[2] = {0.f, 0.f};
    float o[16][4];
    #pragma unroll
    for (int i = 0; i < 16; i++)
        #pragma unroll
        for (int j = 0; j < 4; j++) o[i][j] = 0.f;

    int l15 = lane & 15, lh8 = (lane >> 4) << 3;

    for (int ic = 0; ic < NIT; ic++) {
        if (ic > 0) { cp_wait<0>(); __syncthreads(); }
        uint32_t Kb = smK + (ic & 1) * AKB;
        uint32_t Vb = smV + (ic & 1) * AVB;

        if (ic + 1 < NIT) {
            size_t gk = gk0 + (size_t)(ic + 1) * 64 * DMODEL;
            uint32_t ko = smK + ((ic + 1) & 1) * AKB;
            uint32_t vo = smV + ((ic + 1) & 1) * AVB;
            #pragma unroll
            for (int i = 0; i < 4; i++) {
                int r = sr + 16 * i;
                cpa16(ko + r * 272 + sg * 16, K + gk + (size_t)r * DMODEL + sg * 8);
                cpa16(vo + r * 272 + sg * 16, V + gk + (size_t)r * DMODEL + sg * 8);
            }
            CP_COMMIT();
        }

        float s[8][4];
        #pragma unroll
        for (int nf = 0; nf < 8; nf++)
            #pragma unroll
            for (int j = 0; j < 4; j++) s[nf][j] = 0.f;

        #pragma unroll
        for (int kd = 0; kd < 8; kd++) {
            uint32_t qa[4];
            ldsm4(qa, smQ + ((wid * 16 + l15) * 136 + kd * 16 + lh8) * 2);
            #pragma unroll
            for (int kb = 0; kb < 4; kb++) {
                uint32_t kf[4];
                ldsm4(kf, Kb + ((kb * 16 + (lane & 7) + lh8) * 136
                                + kd * 16 + (lane & 8)) * 2);
                mma_bf(s[kb * 2 + 0], qa, kf + 0);
                mma_bf(s[kb * 2 + 1], qa, kf + 2);
            }
        }

        #pragma unroll
        for (int h2 = 0; h2 < 2; h2++) {
            int base = h2 * 2;
            float mx = -1e30f;
            #pragma unroll
            for (int nf = 0; nf < 8; nf++)
                mx = fmaxf(mx, fmaxf(s[nf][base], s[nf][base + 1]));
            mx = fmaxf(mx, __shfl_xor_sync(0xffffffffu, mx, 1));
            mx = fmaxf(mx, __shfl_xor_sync(0xffffffffu, mx, 2));
            float mnew = fmaxf(mrow[h2], mx);
            float corr = __expf(mrow[h2] - mnew);
            mrow[h2] = mnew;
            float ps = 0.f;
            #pragma unroll
            for (int nf = 0; nf < 8; nf++) {
                float p0 = __expf(s[nf][base]     - mnew);
                float p1 = __expf(s[nf][base + 1] - mnew);
                s[nf][base] = p0; s[nf][base + 1] = p1;
                ps += p0 + p1;
            }
            ps += __shfl_xor_sync(0xffffffffu, ps, 1);
            ps += __shfl_xor_sync(0xffffffffu, ps, 2);
            lrow[h2] = lrow[h2] * corr + ps;
            #pragma unroll
            for (int nf = 0; nf < 16; nf++) {
                o[nf][base]     *= corr;
                o[nf][base + 1] *= corr;
            }
        }

        #pragma unroll
        for (int kc = 0; kc < 4; kc++) {
            uint32_t pa[4] = {
                packbf(s[2 * kc][0],     s[2 * kc][1]),
                packbf(s[2 * kc][2],     s[2 * kc][3]),
                packbf(s[2 * kc + 1][0], s[2 * kc + 1][1]),
                packbf(s[2 * kc + 1][2], s[2 * kc + 1][3]) };
            #pragma unroll
            for (int nb = 0; nb < 8; nb++) {
                uint32_t vb[4];
                ldsm4t(vb, Vb + ((kc * 16 + l15) * 136 + nb * 16 + lh8) * 2);
                mma_bf(o[nb * 2 + 0], pa, vb + 0);
                mma_bf(o[nb * 2 + 1], pa, vb + 2);
            }
        }
    }

    int r4 = lane >> 2, c4 = lane & 3;
    int mq = wid * 16 + r4;
    float inv0 = 1.0f / lrow[0], inv1 = 1.0f / lrow[1];
    #pragma unroll
    for (int nf = 0; nf < 16; nf++) {
        int col = nf * 8 + 2 * c4;
        size_t base0 = gq + (size_t)mq * DMODEL + col;
        *(uint32_t*)&O[base0]              = packbf(o[nf][0] * inv0, o[nf][1] * inv0);
        *(uint32_t*)&O[base0 + 8 * DMODEL] = packbf(o[nf][2] * inv1, o[nf][3] * inv1);
    }
}

// -------- driver -------------------------------------------------------------
extern "C" void kernel_launch(void* const* d_in, const int* in_sizes, int n_in,
                              void* d_out, int out_size) {
    const float* x1    = (const float*)d_in[0];
    const float* x2    = (const float*)d_in[1];
    const float* lnf_g = (const float*)d_in[6];
    const float* lnf_b = (const float*)d_in[7];
    const float* bo    = (const float*)d_in[27];
    const float* b1    = (const float*)d_in[29];
    const float* b2    = (const float*)d_in[31];
    float* out = (float*)d_out;

    bf16 *x1n, *x2n, *q1, *k1, *v1, *q2, *k2, *v2, *ctx1, *ctx2, *src1, *src2, *hbuf, *wr;
    float *xres, *bqkv;
    cudaGetSymbolAddress((void**)&x1n,  g_x1n);
    cudaGetSymbolAddress((void**)&x2n,  g_x2n);
    cudaGetSymbolAddress((void**)&q1,   g_q1);
    cudaGetSymbolAddress((void**)&k1,   g_k1);
    cudaGetSymbolAddress((void**)&v1,   g_v1);
    cudaGetSymbolAddress((void**)&q2,   g_q2);
    cudaGetSymbolAddress((void**)&k2,   g_k2);
    cudaGetSymbolAddress((void**)&v2,   g_v2);
    cudaGetSymbolAddress((void**)&ctx1, g_ctx1);
    cudaGetSymbolAddress((void**)&ctx2, g_ctx2);
    cudaGetSymbolAddress((void**)&src1, g_src1);
    cudaGetSymbolAddress((void**)&src2, g_src2);
    cudaGetSymbolAddress((void**)&xres, g_xres);
    cudaGetSymbolAddress((void**)&hbuf, g_h);
    cudaGetSymbolAddress((void**)&wr,   g_wr);
    cudaGetSymbolAddress((void**)&bqkv, g_bqkv);

    const bf16* Wqkv1  = wr;
    const bf16* Wqkv2  = wr + 786432;
    const bf16* Wqkv12 = wr + 1572864;
    const bf16* Wor    = wr + 2359296;
    const bf16* W1r    = wr + 2621440;
    const bf16* W2r    = wr + 3145728;

    cudaFuncSetAttribute(gemm_bf<0>, cudaFuncAttributeMaxDynamicSharedMemorySize, GEMM_SMEM);
    cudaFuncSetAttribute(gemm_bf<1>, cudaFuncAttributeMaxDynamicSharedMemorySize, GEMM_SMEM);
    cudaFuncSetAttribute(gemm_qkv,   cudaFuncAttributeMaxDynamicSharedMemorySize, QKV_SMEM);
    cudaFuncSetAttribute(gemm_wo,    cudaFuncAttributeMaxDynamicSharedMemorySize, GEMM_SMEM);
    cudaFuncSetAttribute(attn_bf,    cudaFuncAttributeMaxDynamicSharedMemorySize, ATT_SMEM);

    const float qs = 0.08838834764831845f;

    WPtrs wp;
    wp.s[0] = (const float*)d_in[8];  wp.s[1] = (const float*)d_in[10];
    wp.s[2] = (const float*)d_in[12]; wp.s[3] = (const float*)d_in[14];
    wp.s[4] = (const float*)d_in[16]; wp.s[5] = (const float*)d_in[18];
    wp.s[6] = (const float*)d_in[20]; wp.s[7] = (const float*)d_in[22];
    wp.s[8] = (const float*)d_in[24]; wp.s[9] = (const float*)d_in[26];
    wp.s[10] = (const float*)d_in[28]; wp.s[11] = (const float*)d_in[30];
    round_w<<<1792, 256>>>(wp, wr, qs);

    BPtrs bp;
    bp.s[0] = (const float*)d_in[9];  bp.s[1] = (const float*)d_in[11];
    bp.s[2] = (const float*)d_in[13]; bp.s[3] = (const float*)d_in[15];
    bp.s[4] = (const float*)d_in[17]; bp.s[5] = (const float*)d_in[19];
    bp.s[6] = (const float*)d_in[21]; bp.s[7] = (const float*)d_in[23];
    bp.s[8] = (const float*)d_in[25];
    round_b<<<18, 256>>>(bp, bqkv, qs);

    LnA la;
    la.x[0] = x1; la.x[1] = x2;
    la.g[0] = (const float*)d_in[2]; la.g[1] = (const float*)d_in[4];
    la.b[0] = (const float*)d_in[3]; la.b[1] = (const float*)d_in[5];
    la.y[0] = x1n; la.y[1] = x2n;
    ln2_kernel<<<2 * MROWS, 128>>>(la);

    QkvA qa;
    qa.Aq[0] = x1n; qa.Akv[0] = x1n; qa.W[0] = Wqkv1; qa.bias[0] = bqkv;
    qa.q[0] = q1; qa.k[0] = k1; qa.v[0] = v1;
    qa.Aq[1] = x2n; qa.Akv[1] = x2n; qa.W[1] = Wqkv2; qa.bias[1] = bqkv + 1536;
    qa.q[1] = q2; qa.k[1] = k2; qa.v[1] = v2;
    gemm_qkv<<<dim3(24, MROWS / 256), 256, QKV_SMEM>>>(qa, 12);

    AttA aa;
    aa.Q[0] = q1; aa.K[0] = k1; aa.V[0] = v1; aa.O[0] = ctx1;
    aa.Q[1] = q2; aa.K[1] = k2; aa.V[1] = v2; aa.O[1] = ctx2;
    attn_bf<<<dim3(SEQ / 128, NHEAD, 2 * BATCH), 256, ATT_SMEM>>>(aa);

    WoA wo;
    wo.A[0] = ctx1; wo.resid[0] = x1n; wo.out[0] = src1;
    wo.A[1] = ctx2; wo.resid[1] = x2n; wo.out[1] = src2;
    gemm_wo<<<dim3(8, MROWS / 128), 256, GEMM_SMEM>>>(wo, Wor, bo);

    QkvA qc;
    qc.Aq[0] = src1; qc.Akv[0] = src2; qc.W[0] = Wqkv12; qc.bias[0] = bqkv + 3072;
    qc.q[0] = q1; qc.k[0] = k1; qc.v[0] = v1;
    qc.Aq[1] = src1; qc.Akv[1] = src2; qc.W[1] = Wqkv12; qc.bias[1] = bqkv + 3072;
    qc.q[1] = q1; qc.k[1] = k1; qc.v[1] = v1;
    gemm_qkv<<<dim3(12, MROWS / 256), 256, QKV_SMEM>>>(qc, 12);

    AttA ac;
    ac.Q[0] = q1; ac.K[0] = k1; ac.V[0] = v1; ac.O[0] = ctx1;
    ac.Q[1] = q1; ac.K[1] = k1; ac.V[1] = v1; ac.O[1] = ctx1;
    attn_bf<<<dim3(SEQ / 128, NHEAD, BATCH), 256, ATT_SMEM>>>(ac);

    gemm_bf<1><<<dim3(4, MROWS / 128), 256, GEMM_SMEM>>>(
        ctx1, Wor, bo, nullptr, x1, xres, nullptr, MROWS, DMODEL, DMODEL, 0);

    LnA lf;
    lf.x[0] = xres; lf.x[1] = xres;
    lf.g[0] = lnf_g; lf.g[1] = lnf_g;
    lf.b[0] = lnf_b; lf.b[1] = lnf_b;
    lf.y[0] = x1n;  lf.y[1] = x1n;
    ln2_kernel<<<MROWS, 128>>>(lf);

    gemm_bf<0><<<dim3(8, MROWS / 128), 256, GEMM_SMEM>>>(
        x1n, W1r, b1, nullptr, nullptr, nullptr, hbuf, MROWS, DMLP, DMODEL, 1);
    gemm_bf<1><<<dim3(4, MROWS / 128), 256, GEMM_SMEM>>>(
        hbuf, W2r, b2, nullptr, xres, out, nullptr, MROWS, DMODEL, DMLP, 0);
}

// round 16
// speedup vs baseline: 1.0899x; 1.0899x over previous
#include <cuda_runtime.h>
#include <cuda_bf16.h>
#include <math.h>
#include <stdint.h>

#define BATCH 16
#define SEQ   1024
#define DMODEL 512
#define NHEAD 4
#define HDIM  128
#define MROWS (BATCH * SEQ)
#define DMLP  1024

typedef __nv_bfloat16 bf16;

__device__ bf16  g_x1n [MROWS * DMODEL];
__device__ bf16  g_x2n [MROWS * DMODEL];
__device__ bf16  g_q1  [MROWS * DMODEL];
__device__ bf16  g_k1  [MROWS * DMODEL];
__device__ bf16  g_v1  [MROWS * DMODEL];
__device__ bf16  g_q2  [MROWS * DMODEL];
__device__ bf16  g_k2  [MROWS * DMODEL];
__device__ bf16  g_v2  [MROWS * DMODEL];
__device__ bf16  g_ctx1[MROWS * DMODEL];
__device__ bf16  g_ctx2[MROWS * DMODEL];
__device__ bf16  g_src1[MROWS * DMODEL];
__device__ bf16  g_src2[MROWS * DMODEL];
__device__ float g_xres[MROWS * DMODEL];
__device__ bf16  g_h   [MROWS * DMLP];
__device__ bf16  g_wr  [3670016];
__device__ float g_bqkv[4608];

__device__ __forceinline__ uint32_t s2u(const void* p) {
    return (uint32_t)__cvta_generic_to_shared(p);
}
__device__ __forceinline__ void cpa16(uint32_t dst, const void* src) {
    asm volatile("cp.async.cg.shared.global [%0], [%1], 16;" :: "r"(dst), "l"(src));
}
#define CP_COMMIT() asm volatile("cp.async.commit_group;")
template <int N> __device__ __forceinline__ void cp_wait() {
    asm volatile("cp.async.wait_group %0;" :: "n"(N));
}
__device__ __forceinline__ void ldsm4(uint32_t* r, uint32_t a) {
    asm volatile("ldmatrix.sync.aligned.m8n8.x4.shared.b16 {%0,%1,%2,%3}, [%4];"
                 : "=r"(r[0]), "=r"(r[1]), "=r"(r[2]), "=r"(r[3]) : "r"(a));
}
__device__ __forceinline__ void ldsm4t(uint32_t* r, uint32_t a) {
    asm volatile("ldmatrix.sync.aligned.m8n8.x4.trans.shared.b16 {%0,%1,%2,%3}, [%4];"
                 : "=r"(r[0]), "=r"(r[1]), "=r"(r[2]), "=r"(r[3]) : "r"(a));
}
__device__ __forceinline__ void mma_bf(float* c, const uint32_t* a, const uint32_t* b) {
    asm volatile(
        "mma.sync.aligned.m16n8k16.row.col.f32.bf16.bf16.f32 "
        "{%0,%1,%2,%3}, {%4,%5,%6,%7}, {%8,%9}, {%0,%1,%2,%3};"
        : "+f"(c[0]), "+f"(c[1]), "+f"(c[2]), "+f"(c[3])
        : "r"(a[0]), "r"(a[1]), "r"(a[2]), "r"(a[3]), "r"(b[0]), "r"(b[1]));
}
__device__ __forceinline__ uint32_t packbf(float x, float y) {
    __nv_bfloat162 h = __floats2bfloat162_rn(x, y);
    return *(uint32_t*)&h;
}

// -------- weight repack (+ fused bias repack in tail blocks) ----------------
struct WPtrs { const float* s[12]; const float* b[9]; };
__global__ void round_w(WPtrs p, bf16* dst, float* bdst, float qs) {
    int t = blockIdx.x * blockDim.x + threadIdx.x;
    if (t < 458752) {
        int idx = t * 8;
        const float* src; float sc = 1.f; int off;
        if (idx < 2359296) {
            int s = idx / 786432, rem = idx % 786432;
            int kk = rem / 1536, n = rem % 1536;
            int m = n >> 9;
            src = p.s[s * 3 + m];
            off = kk * 512 + (n & 511);
            if (m == 0) sc = qs;
        } else if (idx < 2621440) { src = p.s[9];  off = idx - 2359296; }
        else if (idx < 3145728)   { src = p.s[10]; off = idx - 2621440; }
        else                      { src = p.s[11]; off = idx - 3145728; }
        float4 v0 = *(const float4*)&src[off];
        float4 v1 = *(const float4*)&src[off + 4];
        uint32_t h[4] = { packbf(v0.x*sc, v0.y*sc), packbf(v0.z*sc, v0.w*sc),
                          packbf(v1.x*sc, v1.y*sc), packbf(v1.z*sc, v1.w*sc) };
        *(uint4*)&dst[idx] = *(uint4*)h;
    } else {
        int i = t - 458752;
        if (i >= 4608) return;
        int s = i / 1536, n = i % 1536, m = n >> 9;
        float v = p.b[s * 3 + m][n & 511];
        bdst[i] = (m == 0) ? v * qs : v;
    }
}

// -------- dual LayerNorm -----------------------------------------------------
struct LnA { const float* x[2]; const float* g[2]; const float* b[2]; bf16* y[2]; };
__global__ void ln2_kernel(LnA a) {
    int row = blockIdx.x, t = threadIdx.x;
    int si = row >> 14; row &= (MROWS - 1);
    const float* xr = a.x[si] + (size_t)row * DMODEL;
    float4 v4 = ((const float4*)xr)[t];
    __shared__ float red[4];
    float s = v4.x + v4.y + v4.z + v4.w;
    #pragma unroll
    for (int o = 16; o; o >>= 1) s += __shfl_xor_sync(0xffffffffu, s, o);
    if ((t & 31) == 0) red[t >> 5] = s;
    __syncthreads();
    float mean = (red[0] + red[1] + red[2] + red[3]) * (1.0f / DMODEL);
    __syncthreads();
    float dx = v4.x - mean, dy = v4.y - mean, dz = v4.z - mean, dw = v4.w - mean;
    float vs = dx*dx + dy*dy + dz*dz + dw*dw;
    #pragma unroll
    for (int o = 16; o; o >>= 1) vs += __shfl_xor_sync(0xffffffffu, vs, o);
    if ((t & 31) == 0) red[t >> 5] = vs;
    __syncthreads();
    float var = (red[0] + red[1] + red[2] + red[3]) * (1.0f / DMODEL);
    float inv = rsqrtf(var + 1e-6f);
    float4 g4 = ((const float4*)a.g[si])[t];
    float4 b4 = ((const float4*)a.b[si])[t];
    uint32_t h[2] = { packbf(dx * inv * g4.x + b4.x, dy * inv * g4.y + b4.y),
                      packbf(dz * inv * g4.z + b4.z, dw * inv * g4.w + b4.w) };
    *(uint2*)&a.y[si][(size_t)row * DMODEL + t * 4] = *(uint2*)h;
}

// -------- GEMM tile machinery (BK=64) ---------------------------------------
#define GAB (128 * 144)
#define GBB (64 * 272)
#define GEMM_SMEM (2 * (GAB + GBB))

__device__ __forceinline__ void g_stage(uint32_t smA, uint32_t smB, int buf,
                                        const bf16* A, const bf16* W,
                                        int m0, int n0, int k0, int K, int N, int tid) {
    int ar = tid >> 1, ag = (tid & 1) * 4;
    uint32_t da = smA + buf * GAB + ar * 144 + ag * 16;
    const bf16* sa = A + (size_t)(m0 + ar) * K + k0 + ag * 8;
    #pragma unroll
    for (int i = 0; i < 4; i++) cpa16(da + i * 16, sa + i * 8);
    int br = tid >> 2, bg = (tid & 3) * 4;
    uint32_t db = smB + buf * GBB + br * 272 + bg * 16;
    const bf16* sb = W + (size_t)(k0 + br) * N + n0 + bg * 8;
    #pragma unroll
    for (int i = 0; i < 4; i++) cpa16(db + i * 16, sb + i * 8);
    CP_COMMIT();
}

__device__ __forceinline__ void g_tile(float acc[4][4][4], uint32_t Ab, uint32_t Bb,
                                       int wm, int wn, int l15, int lh8) {
    #pragma unroll
    for (int kk = 0; kk < 64; kk += 16) {
        uint32_t a[4][4];
        #pragma unroll
        for (int mf = 0; mf < 4; mf++)
            ldsm4(a[mf], Ab + ((wm + mf * 16 + l15) * 72 + kk + lh8) * 2);
        #pragma unroll
        for (int nb = 0; nb < 2; nb++) {
            uint32_t b[4];
            ldsm4t(b, Bb + ((kk + l15) * 136 + wn + nb * 16 + lh8) * 2);
            #pragma unroll
            for (int mf = 0; mf < 4; mf++) {
                mma_bf(acc[mf][nb * 2 + 0], a[mf], b + 0);
                mma_bf(acc[mf][nb * 2 + 1], a[mf], b + 2);
            }
        }
    }
}

#define G_PROLOG_COMPUTE(Aptr, Wptr, Nval, Kval)                               \
    float acc[4][4][4];                                                        \
    _Pragma("unroll")                                                          \
    for (int i = 0; i < 4; i++)                                                \
        _Pragma("unroll")                                                      \
        for (int j = 0; j < 4; j++)                                            \
            _Pragma("unroll")                                                  \
            for (int kq = 0; kq < 4; kq++) acc[i][j][kq] = 0.f;                \
    g_stage(smA, smB, 0, Aptr, Wptr, m0, n0, 0, Kval, Nval, tid);              \
    int T = (Kval) >> 6, l15 = lane & 15, lh8 = (lane >> 4) << 3;              \
    for (int it = 0; it < T; it++) {                                           \
        cp_wait<0>();                                                          \
        __syncthreads();                                                       \
        if (it + 1 < T)                                                        \
            g_stage(smA, smB, (it + 1) & 1, Aptr, Wptr, m0, n0,                \
                    (it + 1) * 64, Kval, Nval, tid);                           \
        g_tile(acc, smA + (it & 1) * GAB, smB + (it & 1) * GBB,                \
               wm, wn, l15, lh8);                                              \
        __syncthreads();                                                       \
    }

// -------- generic GEMM (MLP / cross-Wo) -------------------------------------
template<int OUTF32>
__global__ __launch_bounds__(256, 2)
void gemm_bf(const bf16* __restrict__ A, const bf16* __restrict__ W,
             const float* __restrict__ bias,
             const bf16* __restrict__ residh, const float* __restrict__ residf,
             float* __restrict__ Cf, bf16* __restrict__ Ch,
             int M, int N, int K, int gelu) {
    extern __shared__ char smraw[];
    uint32_t smA = s2u(smraw);
    uint32_t smB = smA + 2 * GAB;
    int tid = threadIdx.x, lane = tid & 31, wid = tid >> 5;
    int m0 = blockIdx.y * 128, n0 = blockIdx.x * 128;
    int wm = (wid & 1) * 64, wn = (wid >> 1) * 32;

    G_PROLOG_COMPUTE(A, W, N, K)

    int r4 = lane >> 2, c2 = (lane & 3) * 2;
    #pragma unroll
    for (int mf = 0; mf < 4; mf++) {
        #pragma unroll
        for (int nf = 0; nf < 4; nf++) {
            int row = m0 + wm + mf * 16 + r4;
            int col = n0 + wn + nf * 8 + c2;
            float2 bi = *(const float2*)&bias[col];
            #pragma unroll
            for (int hh = 0; hh < 2; hh++) {
                int r = row + hh * 8;
                float v0 = acc[mf][nf][hh * 2 + 0] + bi.x;
                float v1 = acc[mf][nf][hh * 2 + 1] + bi.y;
                if (residh) {
                    uint32_t rp = *(const uint32_t*)&residh[(size_t)r * N + col];
                    float2 rr = __bfloat1622float2(*(__nv_bfloat162*)&rp);
                    v0 += rr.x; v1 += rr.y;
                }
                if (residf) {
                    float2 rr = *(const float2*)&residf[(size_t)r * N + col];
                    v0 += rr.x; v1 += rr.y;
                }
                if (gelu) {
                    v0 = 0.5f * v0 * (1.0f + erff(v0 * 0.70710678118654752f));
                    v1 = 0.5f * v1 * (1.0f + erff(v1 * 0.70710678118654752f));
                }
                if (OUTF32) *(float2*)&Cf[(size_t)r * N + col] = make_float2(v0, v1);
                else *(uint32_t*)&Ch[(size_t)r * N + col] = packbf(v0, v1);
            }
        }
    }
}

// -------- fused QKV GEMM, dual-stream (locked R11 form) ----------------------
struct QkvA {
    const bf16* Aq[2]; const bf16* Akv[2]; const bf16* W[2];
    const float* bias[2]; bf16* q[2]; bf16* k[2]; bf16* v[2];
};
__global__ __launch_bounds__(256, 2)
void gemm_qkv(QkvA p) {
    const int K = DMODEL, N = 1536;
    extern __shared__ char smraw[];
    uint32_t smA = s2u(smraw);
    uint32_t smB = smA + 2 * GAB;
    int tid = threadIdx.x, lane = tid & 31, wid = tid >> 5;
    int nb12 = blockIdx.x;
    int si = nb12 / 12;
    int n0 = (nb12 % 12) * 128, m0 = blockIdx.y * 128;
    const bf16* A = (n0 < 512) ? p.Aq[si] : p.Akv[si];
    const bf16* W = p.W[si];
    int wm = (wid & 1) * 64, wn = (wid >> 1) * 32;

    G_PROLOG_COMPUTE(A, W, N, K)

    int r4 = lane >> 2, c2 = (lane & 3) * 2;
    #pragma unroll
    for (int mf = 0; mf < 4; mf++) {
        #pragma unroll
        for (int nf = 0; nf < 4; nf++) {
            int row = m0 + wm + mf * 16 + r4;
            int col = n0 + wn + nf * 8 + c2;
            bf16* dst = (col < 512) ? p.q[si] : (col < 1024) ? p.k[si] : p.v[si];
            int cc = col & 511;
            float2 bi = *(const float2*)&p.bias[si][col];
            #pragma unroll
            for (int hh = 0; hh < 2; hh++) {
                int r = row + hh * 8;
                float v0 = acc[mf][nf][hh * 2 + 0] + bi.x;
                float v1 = acc[mf][nf][hh * 2 + 1] + bi.y;
                *(uint32_t*)&dst[(size_t)r * DMODEL + cc] = packbf(v0, v1);
            }
        }
    }
}

// -------- fused Wo GEMM, dual-stream -----------------------------------------
struct WoA { const bf16* A[2]; const bf16* resid[2]; bf16* out[2]; };
__global__ __launch_bounds__(256, 2)
void gemm_wo(WoA p, const bf16* __restrict__ W, const float* __restrict__ bias) {
    const int K = DMODEL, N = DMODEL;
    extern __shared__ char smraw[];
    uint32_t smA = s2u(smraw);
    uint32_t smB = smA + 2 * GAB;
    int tid = threadIdx.x, lane = tid & 31, wid = tid >> 5;
    int si = blockIdx.x >> 2;
    int n0 = (blockIdx.x & 3) * 128, m0 = blockIdx.y * 128;
    const bf16* A = p.A[si];
    int wm = (wid & 1) * 64, wn = (wid >> 1) * 32;

    G_PROLOG_COMPUTE(A, W, N, K)

    int r4 = lane >> 2, c2 = (lane & 3) * 2;
    #pragma unroll
    for (int mf = 0; mf < 4; mf++) {
        #pragma unroll
        for (int nf = 0; nf < 4; nf++) {
            int row = m0 + wm + mf * 16 + r4;
            int col = n0 + wn + nf * 8 + c2;
            float2 bi = *(const float2*)&bias[col];
            #pragma unroll
            for (int hh = 0; hh < 2; hh++) {
                int r = row + hh * 8;
                uint32_t rp = *(const uint32_t*)&p.resid[si][(size_t)r * N + col];
                float2 rr = __bfloat1622float2(*(__nv_bfloat162*)&rp);
                float v0 = acc[mf][nf][hh * 2 + 0] + bi.x + rr.x;
                float v1 = acc[mf][nf][hh * 2 + 1] + bi.y + rr.y;
                *(uint32_t*)&p.out[si][(size_t)r * N + col] = packbf(v0, v1);
            }
        }
    }
}

// -------- bf16 flash attention (locked R11 form) -----------------------------
#define AQB (128 * 272)
#define AKB (64 * 272)
#define AVB (64 * 272)
#define ATT_SMEM (AQB + 2 * AKB + 2 * AVB)
#define NIT (SEQ / 64)

struct AttA { const bf16* Q[2]; const bf16* K[2]; const bf16* V[2]; bf16* O[2]; };
__global__ __launch_bounds__(256, 2)
void attn_bf(AttA p) {
    extern __shared__ char smraw[];
    uint32_t smQ = s2u(smraw);
    uint32_t smK = smQ + AQB;
    uint32_t smV = smK + 2 * AKB;

    int tid = threadIdx.x, lane = tid & 31, wid = tid >> 5;
    int q0 = blockIdx.x * 128, h = blockIdx.y;
    int zi = blockIdx.z;
    int si = zi >> 4, b = zi & 15;
    const bf16* Q = p.Q[si];
    const bf16* K = p.K[si];
    const bf16* V = p.V[si];
    bf16* O = p.O[si];
    size_t gq  = ((size_t)b * SEQ + q0) * DMODEL + (size_t)h * HDIM;
    size_t gk0 = ((size_t)b * SEQ) * DMODEL + (size_t)h * HDIM;
    int sr = tid >> 4, sg = tid & 15;

    #pragma unroll
    for (int i = 0; i < 8; i++) {
        int r = sr + 16 * i;
        cpa16(smQ + r * 272 + sg * 16, Q + gq + (size_t)r * DMODEL + sg * 8);
    }
    CP_COMMIT();
    #pragma unroll
    for (int i = 0; i < 4; i++) {
        int r = sr + 16 * i;
        cpa16(smK + r * 272 + sg * 16, K + gk0 + (size_t)r * DMODEL + sg * 8);
        cpa16(smV + r * 272 + sg * 16, V + gk0 + (size_t)r * DMODEL + sg * 8);
    }
    CP_COMMIT();
    cp_wait<0>();
    __syncthreads();

    float mrow[2] = {-1e30f, -1e30f}, lrow[2] = {0.f, 0.f};
    float o[16][4];
    #pragma unroll
    for (int i = 0; i < 16; i++)
        #pragma unroll
        for (int j = 0; j < 4; j++) o[i][j] = 0.f;

    int l15 = lane & 15, lh8 = (lane >> 4) << 3;

    for (int ic = 0; ic < NIT; ic++) {
        if (ic > 0) { cp_wait<0>(); __syncthreads(); }
        uint32_t Kb = smK + (ic & 1) * AKB;
        uint32_t Vb = smV + (ic & 1) * AVB;

        if (ic + 1 < NIT) {
            size_t gk = gk0 + (size_t)(ic + 1) * 64 * DMODEL;
            uint32_t ko = smK + ((ic + 1) & 1) * AKB;
            uint32_t vo = smV + ((ic + 1) & 1) * AVB;
            #pragma unroll
            for (int i = 0; i < 4; i++) {
                int r = sr + 16 * i;
                cpa16(ko + r * 272 + sg * 16, K + gk + (size_t)r * DMODEL + sg * 8);
                cpa16(vo + r * 272 + sg * 16, V + gk + (size_t)r * DMODEL + sg * 8);
            }
            CP_COMMIT();
        }

        float s[8][4];
        #pragma unroll
        for (int nf = 0; nf < 8; nf++)
            #pragma unroll
            for (int j = 0; j < 4; j++) s[nf][j] = 0.f;

        #pragma unroll
        for (int kd = 0; kd < 8; kd++) {
            uint32_t qa[4];
            ldsm4(qa, smQ + ((wid * 16 + l15) * 136 + kd * 16 + lh8) * 2);
            #pragma unroll
            for (int kb = 0; kb < 4; kb++) {
                uint32_t kf[4];
                ldsm4(kf, Kb + ((kb * 16 + (lane & 7) + lh8) * 136
                                + kd * 16 + (lane & 8)) * 2);
                mma_bf(s[kb * 2 + 0], qa, kf + 0);
                mma_bf(s[kb * 2 + 1], qa, kf + 2);
            }
        }

        #pragma unroll
        for (int h2 = 0; h2 < 2; h2++) {
            int base = h2 * 2;
            float mx = -1e30f;
            #pragma unroll
            for (int nf = 0; nf < 8; nf++)
                mx = fmaxf(mx, fmaxf(s[nf][base], s[nf][base + 1]));
            mx = fmaxf(mx, __shfl_xor_sync(0xffffffffu, mx, 1));
            mx = fmaxf(mx, __shfl_xor_sync(0xffffffffu, mx, 2));
            float mnew = fmaxf(mrow[h2], mx);
            float corr = __expf(mrow[h2] - mnew);
            mrow[h2] = mnew;
            float ps = 0.f;
            #pragma unroll
            for (int nf = 0; nf < 8; nf++) {
                float p0 = __expf(s[nf][base]     - mnew);
                float p1 = __expf(s[nf][base + 1] - mnew);
                s[nf][base] = p0; s[nf][base + 1] = p1;
                ps += p0 + p1;
            }
            ps += __shfl_xor_sync(0xffffffffu, ps, 1);
            ps += __shfl_xor_sync(0xffffffffu, ps, 2);
            lrow[h2] = lrow[h2] * corr + ps;
            #pragma unroll
            for (int nf = 0; nf < 16; nf++) {
                o[nf][base]     *= corr;
                o[nf][base + 1] *= corr;
            }
        }

        #pragma unroll
        for (int kc = 0; kc < 4; kc++) {
            uint32_t pa[4] = {
                packbf(s[2 * kc][0],     s[2 * kc][1]),
                packbf(s[2 * kc][2],     s[2 * kc][3]),
                packbf(s[2 * kc + 1][0], s[2 * kc + 1][1]),
                packbf(s[2 * kc + 1][2], s[2 * kc + 1][3]) };
            #pragma unroll
            for (int nb = 0; nb < 8; nb++) {
                uint32_t vb[4];
                ldsm4t(vb, Vb + ((kc * 16 + l15) * 136 + nb * 16 + lh8) * 2);
                mma_bf(o[nb * 2 + 0], pa, vb + 0);
                mma_bf(o[nb * 2 + 1], pa, vb + 2);
            }
        }
    }

    int r4 = lane >> 2, c4 = lane & 3;
    int mq = wid * 16 + r4;
    float inv0 = 1.0f / lrow[0], inv1 = 1.0f / lrow[1];
    #pragma unroll
    for (int nf = 0; nf < 16; nf++) {
        int col = nf * 8 + 2 * c4;
        size_t base0 = gq + (size_t)mq * DMODEL + col;
        *(uint32_t*)&O[base0]              = packbf(o[nf][0] * inv0, o[nf][1] * inv0);
        *(uint32_t*)&O[base0 + 8 * DMODEL] = packbf(o[nf][2] * inv1, o[nf][3] * inv1);
    }
}

// -------- driver -------------------------------------------------------------
extern "C" void kernel_launch(void* const* d_in, const int* in_sizes, int n_in,
                              void* d_out, int out_size) {
    const float* x1    = (const float*)d_in[0];
    const float* x2    = (const float*)d_in[1];
    const float* lnf_g = (const float*)d_in[6];
    const float* lnf_b = (const float*)d_in[7];
    const float* bo    = (const float*)d_in[27];
    const float* b1    = (const float*)d_in[29];
    const float* b2    = (const float*)d_in[31];
    float* out = (float*)d_out;

    bf16 *x1n, *x2n, *q1, *k1, *v1, *q2, *k2, *v2, *ctx1, *ctx2, *src1, *src2, *hbuf, *wr;
    float *xres, *bqkv;
    cudaGetSymbolAddress((void**)&x1n,  g_x1n);
    cudaGetSymbolAddress((void**)&x2n,  g_x2n);
    cudaGetSymbolAddress((void**)&q1,   g_q1);
    cudaGetSymbolAddress((void**)&k1,   g_k1);
    cudaGetSymbolAddress((void**)&v1,   g_v1);
    cudaGetSymbolAddress((void**)&q2,   g_q2);
    cudaGetSymbolAddress((void**)&k2,   g_k2);
    cudaGetSymbolAddress((void**)&v2,   g_v2);
    cudaGetSymbolAddress((void**)&ctx1, g_ctx1);
    cudaGetSymbolAddress((void**)&ctx2, g_ctx2);
    cudaGetSymbolAddress((void**)&src1, g_src1);
    cudaGetSymbolAddress((void**)&src2, g_src2);
    cudaGetSymbolAddress((void**)&xres, g_xres);
    cudaGetSymbolAddress((void**)&hbuf, g_h);
    cudaGetSymbolAddress((void**)&wr,   g_wr);
    cudaGetSymbolAddress((void**)&bqkv, g_bqkv);

    const bf16* Wqkv1  = wr;
    const bf16* Wqkv2  = wr + 786432;
    const bf16* Wqkv12 = wr + 1572864;
    const bf16* Wor    = wr + 2359296;
    const bf16* W1r    = wr + 2621440;
    const bf16* W2r    = wr + 3145728;

    cudaFuncSetAttribute(gemm_bf<0>, cudaFuncAttributeMaxDynamicSharedMemorySize, GEMM_SMEM);
    cudaFuncSetAttribute(gemm_bf<1>, cudaFuncAttributeMaxDynamicSharedMemorySize, GEMM_SMEM);
    cudaFuncSetAttribute(gemm_qkv,   cudaFuncAttributeMaxDynamicSharedMemorySize, GEMM_SMEM);
    cudaFuncSetAttribute(gemm_wo,    cudaFuncAttributeMaxDynamicSharedMemorySize, GEMM_SMEM);
    cudaFuncSetAttribute(attn_bf,    cudaFuncAttributeMaxDynamicSharedMemorySize, ATT_SMEM);

    const float qs = 0.08838834764831845f;

    WPtrs wp;
    wp.s[0] = (const float*)d_in[8];  wp.s[1] = (const float*)d_in[10];
    wp.s[2] = (const float*)d_in[12]; wp.s[3] = (const float*)d_in[14];
    wp.s[4] = (const float*)d_in[16]; wp.s[5] = (const float*)d_in[18];
    wp.s[6] = (const float*)d_in[20]; wp.s[7] = (const float*)d_in[22];
    wp.s[8] = (const float*)d_in[24]; wp.s[9] = (const float*)d_in[26];
    wp.s[10] = (const float*)d_in[28]; wp.s[11] = (const float*)d_in[30];
    wp.b[0] = (const float*)d_in[9];  wp.b[1] = (const float*)d_in[11];
    wp.b[2] = (const float*)d_in[13]; wp.b[3] = (const float*)d_in[15];
    wp.b[4] = (const float*)d_in[17]; wp.b[5] = (const float*)d_in[19];
    wp.b[6] = (const float*)d_in[21]; wp.b[7] = (const float*)d_in[23];
    wp.b[8] = (const float*)d_in[25];
    round_w<<<1811, 256>>>(wp, wr, bqkv, qs);

    LnA la;
    la.x[0] = x1; la.x[1] = x2;
    la.g[0] = (const float*)d_in[2]; la.g[1] = (const float*)d_in[4];
    la.b[0] = (const float*)d_in[3]; la.b[1] = (const float*)d_in[5];
    la.y[0] = x1n; la.y[1] = x2n;
    ln2_kernel<<<2 * MROWS, 128>>>(la);

    QkvA qa;
    qa.Aq[0] = x1n; qa.Akv[0] = x1n; qa.W[0] = Wqkv1; qa.bias[0] = bqkv;
    qa.q[0] = q1; qa.k[0] = k1; qa.v[0] = v1;
    qa.Aq[1] = x2n; qa.Akv[1] = x2n; qa.W[1] = Wqkv2; qa.bias[1] = bqkv + 1536;
    qa.q[1] = q2; qa.k[1] = k2; qa.v[1] = v2;
    gemm_qkv<<<dim3(24, MROWS / 128), 256, GEMM_SMEM>>>(qa);

    AttA aa;
    aa.Q[0] = q1; aa.K[0] = k1; aa.V[0] = v1; aa.O[0] = ctx1;
    aa.Q[1] = q2; aa.K[1] = k2; aa.V[1] = v2; aa.O[1] = ctx2;
    attn_bf<<<dim3(SEQ / 128, NHEAD, 2 * BATCH), 256, ATT_SMEM>>>(aa);

    WoA wo;
    wo.A[0] = ctx1; wo.resid[0] = x1n; wo.out[0] = src1;
    wo.A[1] = ctx2; wo.resid[1] = x2n; wo.out[1] = src2;
    gemm_wo<<<dim3(8, MROWS / 128), 256, GEMM_SMEM>>>(wo, Wor, bo);

    QkvA qc;
    qc.Aq[0] = src1; qc.Akv[0] = src2; qc.W[0] = Wqkv12; qc.bias[0] = bqkv + 3072;
    qc.q[0] = q1; qc.k[0] = k1; qc.v[0] = v1;
    qc.Aq[1] = src1; qc.Akv[1] = src2; qc.W[1] = Wqkv12; qc.bias[1] = bqkv + 3072;
    qc.q[1] = q1; qc.k[1] = k1; qc.v[1] = v1;
    gemm_qkv<<<dim3(12, MROWS / 128), 256, GEMM_SMEM>>>(qc);

    AttA ac;
    ac.Q[0] = q1; ac.K[0] = k1; ac.V[0] = v1; ac.O[0] = ctx1;
    ac.Q[1] = q1; ac.K[1] = k1; ac.V[1] = v1; ac.O[1] = ctx1;
    attn_bf<<<dim3(SEQ / 128, NHEAD, BATCH), 256, ATT_SMEM>>>(ac);

    gemm_bf<1><<<dim3(4, MROWS / 128), 256, GEMM_SMEM>>>(
        ctx1, Wor, bo, nullptr, x1, xres, nullptr, MROWS, DMODEL, DMODEL, 0);

    LnA lf;
    lf.x[0] = xres; lf.x[1] = xres;
    lf.g[0] = lnf_g; lf.g[1] = lnf_g;
    lf.b[0] = lnf_b; lf.b[1] = lnf_b;
    lf.y[0] = x1n;  lf.y[1] = x1n;
    ln2_kernel<<<MROWS, 128>>>(lf);

    gemm_bf<0><<<dim3(8, MROWS / 128), 256, GEMM_SMEM>>>(
        x1n, W1r, b1, nullptr, nullptr, nullptr, hbuf, MROWS, DMLP, DMODEL, 1);
    gemm_bf<1><<<dim3(4, MROWS / 128), 256, GEMM_SMEM>>>(
        hbuf, W2r, b2, nullptr, xres, out, nullptr, MROWS, DMODEL, DMLP, 0);
}